// round 5
// baseline (speedup 1.0000x reference)
#include <cuda_runtime.h>
#include <math.h>

#define BB 128
#define LL 512
#define DD 128
#define BL (BB*LL)
#define ML 512

// ---------------- scratch (static device globals; no allocations) ----------------
__device__ float g_seqs[BL*DD];
__device__ float g_Q   [BL*DD];
__device__ float g_q   [BL*DD];
__device__ float g_k   [BL*DD];
__device__ float g_v   [BL*DD];
__device__ float g_qp  [BL*DD];
__device__ float g_mha [BL*DD];
__device__ float g_tmp [BL*DD];
__device__ float g_E   [BL*ML];
__device__ float g_cape[BL];

// ---------------- helpers ----------------
__device__ __forceinline__ float wredsum(float v){
    #pragma unroll
    for (int o=16;o>0;o>>=1) v += __shfl_xor_sync(0xffffffffu, v, o);
    return v;
}
__device__ __forceinline__ float wredmax(float v){
    #pragma unroll
    for (int o=16;o>0;o>>=1) v = fmaxf(v, __shfl_xor_sync(0xffffffffu, v, o));
    return v;
}
__device__ __forceinline__ void mma_tf32(float* d, const unsigned* a, const unsigned* b){
    asm volatile(
        "mma.sync.aligned.m16n8k8.row.col.f32.tf32.tf32.f32 "
        "{%0,%1,%2,%3},{%4,%5,%6,%7},{%8,%9},{%0,%1,%2,%3};"
        : "+f"(d[0]),"+f"(d[1]),"+f"(d[2]),"+f"(d[3])
        : "r"(a[0]),"r"(a[1]),"r"(a[2]),"r"(a[3]), "r"(b[0]),"r"(b[1]));
}
__device__ __forceinline__ void cpa16(void* s, const void* g){
    unsigned sa = (unsigned)__cvta_generic_to_shared(s);
    asm volatile("cp.async.cg.shared.global [%0],[%1],16;\n" :: "r"(sa),"l"(g));
}
__device__ __forceinline__ void cp_commit(){ asm volatile("cp.async.commit_group;\n"); }
template<int N> __device__ __forceinline__ void cp_wait(){ asm volatile("cp.async.wait_group %0;\n"::"n"(N)); }
__device__ __forceinline__ unsigned fu(float f){ return __float_as_uint(f); }

// ---------------- embedding gather ----------------
__global__ void embed_k(const float* __restrict__ item, const int* __restrict__ idx,
                        float* __restrict__ out){
    int row  = blockIdx.x*8 + (threadIdx.x>>5);
    int lane = threadIdx.x & 31;
    int id = idx[row];
    float4 v = *(const float4*)(item + (long long)id*DD + lane*4);
    const float s = 11.313708498984760f; // sqrt(128)
    v.x*=s; v.y*=s; v.z*=s; v.w*=s;
    *(float4*)(out + (long long)row*DD + lane*4) = v;
}

// ---------------- layernorm (optionally add per-row cape scalar first) ----------------
template<bool ADDC>
__global__ void ln_k(const float* __restrict__ x, const float* __restrict__ cape,
                     const float* __restrict__ gs, const float* __restrict__ gb,
                     float* __restrict__ y){
    int row  = blockIdx.x*8 + (threadIdx.x>>5);
    int lane = threadIdx.x & 31;
    const float* xr = x + (long long)row*DD;
    float4 v = *(const float4*)(xr + lane*4);
    if (ADDC){ float c = cape[row]; v.x+=c; v.y+=c; v.z+=c; v.w+=c; }
    float m = wredsum(v.x+v.y+v.z+v.w) * (1.0f/DD);
    float dx=v.x-m, dy=v.y-m, dz=v.z-m, dw=v.w-m;
    float var = wredsum(dx*dx+dy*dy+dz*dz+dw*dw) * (1.0f/DD);
    float r = rsqrtf(var + 1e-8f);
    float4 o;
    o.x = dx*r*gs[lane*4+0] + gb[lane*4+0];
    o.y = dy*r*gs[lane*4+1] + gb[lane*4+1];
    o.z = dz*r*gs[lane*4+2] + gb[lane*4+2];
    o.w = dw*r*gs[lane*4+3] + gb[lane*4+3];
    *(float4*)(y + (long long)row*DD + lane*4) = o;
}

// ---------------- final: LN + dot with pos/neg item embeddings ----------------
__global__ void final_k(const float* __restrict__ seqs, const float* __restrict__ item,
                        const float* __restrict__ gs, const float* __restrict__ gb,
                        const int* __restrict__ pos, const int* __restrict__ neg,
                        float* __restrict__ out){
    int row  = blockIdx.x*8 + (threadIdx.x>>5);
    int lane = threadIdx.x & 31;
    const float* xr = seqs + (long long)row*DD;
    float4 v = *(const float4*)(xr + lane*4);
    float m = wredsum(v.x+v.y+v.z+v.w) * (1.0f/DD);
    float dx=v.x-m, dy=v.y-m, dz=v.z-m, dw=v.w-m;
    float var = wredsum(dx*dx+dy*dy+dz*dz+dw*dw) * (1.0f/DD);
    float r = rsqrtf(var + 1e-8f);
    float f0 = dx*r*gs[lane*4+0] + gb[lane*4+0];
    float f1 = dy*r*gs[lane*4+1] + gb[lane*4+1];
    float f2 = dz*r*gs[lane*4+2] + gb[lane*4+2];
    float f3 = dw*r*gs[lane*4+3] + gb[lane*4+3];
    int pi = pos[row], ni = neg[row];
    float4 pe = *(const float4*)(item + (long long)pi*DD + lane*4);
    float4 ne = *(const float4*)(item + (long long)ni*DD + lane*4);
    float dp = f0*pe.x + f1*pe.y + f2*pe.z + f3*pe.w;
    float dn = f0*ne.x + f1*ne.y + f2*ne.z + f3*ne.w;
    dp = wredsum(dp); dn = wredsum(dn);
    if (lane==0){ out[row] = dp; out[BL+row] = dn; }
}

// ---------------- pipelined TF32 GEMM: C = act(alpha*A.op(B)+bias)+res ----------------
// A [M,K] row-major. TRANSB: B [N,K] (C=A.B^T), else B [K,N]. cp.async 2-stage.
// 128x128x16 tiles, 256 thr, warp tile 64x32. K%16==0, M%128==0, N%128==0.
template<bool TRANSB, int ACT>
__global__ __launch_bounds__(256,2)
void gemm_p(const float* __restrict__ A, const float* __restrict__ Bm,
            const float* __restrict__ bias, const float* __restrict__ res,
            float* __restrict__ C, int M, int N, int K, float alpha)
{
    __shared__ __align__(16) float As[2][128*20];
    __shared__ __align__(16) float Bs[2][2560];
    const int tid=threadIdx.x, warp=tid>>5, lane=tid&31;
    const int wm=(warp&1)*64, wn=(warp>>1)*32;
    const int m0=blockIdx.y*128, n0=blockIdx.x*128;
    const int ar=lane>>2, ac=lane&3;
    const int nk=K>>4;

    float acc[4][4][4];
    #pragma unroll
    for (int i=0;i<4;i++)
        #pragma unroll
        for (int j=0;j<4;j++)
            #pragma unroll
            for (int r=0;r<4;r++) acc[i][j][r]=0.f;

    // stage 0 loads
    {
        #pragma unroll
        for (int p=0;p<2;p++){
            int t=p*256+tid, row=t>>2, c4=(t&3)*4;
            cpa16(&As[0][row*20+c4], A + (long long)(m0+row)*K + c4);
        }
        if (TRANSB){
            #pragma unroll
            for (int p=0;p<2;p++){
                int t=p*256+tid, row=t>>2, c4=(t&3)*4;
                cpa16(&Bs[0][row*20+c4], Bm + (long long)(n0+row)*K + c4);
            }
        } else {
            #pragma unroll
            for (int p=0;p<2;p++){
                int t=p*256+tid, kk=t>>5, c4=(t&31)*4;
                cpa16(&Bs[0][kk*136+c4], Bm + (long long)kk*N + n0 + c4);
            }
        }
        cp_commit();
    }

    for (int i=0;i<nk;i++){
        if (i+1<nk){
            int bn=(i+1)&1, k0=(i+1)<<4;
            #pragma unroll
            for (int p=0;p<2;p++){
                int t=p*256+tid, row=t>>2, c4=(t&3)*4;
                cpa16(&As[bn][row*20+c4], A + (long long)(m0+row)*K + k0 + c4);
            }
            if (TRANSB){
                #pragma unroll
                for (int p=0;p<2;p++){
                    int t=p*256+tid, row=t>>2, c4=(t&3)*4;
                    cpa16(&Bs[bn][row*20+c4], Bm + (long long)(n0+row)*K + k0 + c4);
                }
            } else {
                #pragma unroll
                for (int p=0;p<2;p++){
                    int t=p*256+tid, kk=t>>5, c4=(t&31)*4;
                    cpa16(&Bs[bn][kk*136+c4], Bm + (long long)(k0+kk)*N + n0 + c4);
                }
            }
            cp_commit();
            cp_wait<1>();
        } else {
            cp_wait<0>();
        }
        __syncthreads();
        const int bc=i&1;
        #pragma unroll
        for (int s8=0;s8<2;s8++){
            const int kb=s8*8;
            unsigned af[4][4];
            #pragma unroll
            for (int mi=0;mi<4;mi++){
                int r0=wm+mi*16+ar;
                af[mi][0]=fu(As[bc][(r0  )*20+kb+ac  ]);
                af[mi][1]=fu(As[bc][(r0+8)*20+kb+ac  ]);
                af[mi][2]=fu(As[bc][(r0  )*20+kb+ac+4]);
                af[mi][3]=fu(As[bc][(r0+8)*20+kb+ac+4]);
            }
            #pragma unroll
            for (int ni=0;ni<4;ni++){
                unsigned bf[2];
                if (TRANSB){
                    int nr=wn+ni*8+ar;
                    bf[0]=fu(Bs[bc][nr*20+kb+ac  ]);
                    bf[1]=fu(Bs[bc][nr*20+kb+ac+4]);
                } else {
                    int nc=wn+ni*8+ar;
                    bf[0]=fu(Bs[bc][(kb+ac  )*136+nc]);
                    bf[1]=fu(Bs[bc][(kb+ac+4)*136+nc]);
                }
                #pragma unroll
                for (int mi=0;mi<4;mi++) mma_tf32(acc[mi][ni], af[mi], bf);
            }
        }
        __syncthreads();
    }

    const int er=lane>>2, ec=(lane&3)*2;
    #pragma unroll
    for (int mi=0;mi<4;mi++){
        #pragma unroll
        for (int half=0; half<2; half++){
            long long gm = m0 + wm + mi*16 + er + half*8;
            float* crow = C + gm*(long long)N;
            const float* rrow = res ? (res + gm*(long long)N) : nullptr;
            #pragma unroll
            for (int ni=0;ni<4;ni++){
                int gn = n0 + wn + ni*8 + ec;
                float v0 = acc[mi][ni][half*2+0]*alpha;
                float v1 = acc[mi][ni][half*2+1]*alpha;
                if (bias){ v0 += bias[gn]; v1 += bias[gn+1]; }
                if (ACT==1){ v0 = fmaxf(v0,0.f); v1 = fmaxf(v1,0.f); }
                if (ACT==2){ v0 = v0/(1.0f+expf(-v0)); v1 = v1/(1.0f+expf(-v1)); }
                if (rrow){ v0 += rrow[gn]; v1 += rrow[gn+1]; }
                float2 o; o.x=v0; o.y=v1;
                *(float2*)(crow + gn) = o;
            }
        }
    }
}

// ---------------- fused attention: scores -> softmax -> CAPE -> attn@V ----------------
// One CTA = 64 q-rows of one batch. Scores never leave SMEM.
// grid (8 q-tiles, 128 batches), 256 threads.
#define SWS 516
__global__ __launch_bounds__(256,1)
void attn_fused(const float* __restrict__ q, const float* __restrict__ kmat,
                const float* __restrict__ v, const float* __restrict__ E,
                float* __restrict__ cape, float* __restrict__ mha, float scale)
{
    extern __shared__ float sm[];
    float*    S  = sm;                          // [64][516] scores/probs
    unsigned* QS = (unsigned*)(sm + 64*SWS);    // [128][72] q (d-major)   \ union
    unsigned* KS = QS + 128*72;                 // [128][72] k tile        |
    float*    EB = (float*)QS;                  // [8][512] E rows         |
    float*    GS = (float*)QS + 8*512;          // [8][32*17] G staging    |
    unsigned* VS = (unsigned*)QS;               // [16][136] v tile        /

    const int tid=threadIdx.x, warp=tid>>5, lane=tid&31;
    const int qt=blockIdx.x, b=blockIdx.y;
    const int q0=qt*64;
    const int ar=lane>>2, ac=lane&3;

    // load q tile -> QS[d][m]
    {
        int row=tid>>2, c4=(tid&3)*4;
        const float* qrow = q + ((long long)(b*LL + q0 + row))*DD;
        #pragma unroll
        for (int p=0;p<8;p++){
            int d0=p*16;
            float4 a = *(const float4*)(qrow + d0 + c4);
            QS[(d0+c4+0)*72+row]=fu(a.x); QS[(d0+c4+1)*72+row]=fu(a.y);
            QS[(d0+c4+2)*72+row]=fu(a.z); QS[(d0+c4+3)*72+row]=fu(a.w);
        }
    }

    // ---- phase 1: scores = q.k^T * scale into S ----
    const int wm1=(warp&3)*16, wn1=(warp>>2)*32;
    for (int kt=0; kt<=qt; kt++){
        __syncthreads();
        {
            int row=tid>>2, c4=(tid&3)*4;
            const float* krow = kmat + ((long long)(b*LL + kt*64 + row))*DD;
            #pragma unroll
            for (int p=0;p<8;p++){
                int d0=p*16;
                float4 a = *(const float4*)(krow + d0 + c4);
                KS[(d0+c4+0)*72+row]=fu(a.x); KS[(d0+c4+1)*72+row]=fu(a.y);
                KS[(d0+c4+2)*72+row]=fu(a.z); KS[(d0+c4+3)*72+row]=fu(a.w);
            }
        }
        __syncthreads();
        float acc[4][4];
        #pragma unroll
        for (int ni=0;ni<4;ni++)
            #pragma unroll
            for (int r=0;r<4;r++) acc[ni][r]=0.f;
        #pragma unroll
        for (int s8=0;s8<16;s8++){
            int kb=s8*8;
            unsigned af[4];
            af[0]=QS[(kb+ac  )*72 + wm1+ar  ];
            af[1]=QS[(kb+ac  )*72 + wm1+ar+8];
            af[2]=QS[(kb+ac+4)*72 + wm1+ar  ];
            af[3]=QS[(kb+ac+4)*72 + wm1+ar+8];
            #pragma unroll
            for (int ni=0;ni<4;ni++){
                unsigned bf[2];
                bf[0]=KS[(kb+ac  )*72 + wn1+ni*8+ar];
                bf[1]=KS[(kb+ac+4)*72 + wn1+ni*8+ar];
                mma_tf32(acc[ni], af, bf);
            }
        }
        #pragma unroll
        for (int ni=0;ni<4;ni++){
            int col = kt*64 + wn1 + ni*8 + ac*2;
            S[(wm1+ar  )*SWS + col  ] = acc[ni][0]*scale;
            S[(wm1+ar  )*SWS + col+1] = acc[ni][1]*scale;
            S[(wm1+ar+8)*SWS + col  ] = acc[ni][2]*scale;
            S[(wm1+ar+8)*SWS + col+1] = acc[ni][3]*scale;
        }
    }
    __syncthreads();

    // ---- phase 2+3: per-row softmax (masked->0) then CAPE ----
    float* gs_ = GS + warp*544;
    float* eb_ = EB + warp*512;
    for (int i=0;i<8;i++){
        int r = warp*8 + i;
        int qi = q0 + r;
        int nv = qi + 1;
        float* p = S + r*SWS;
        float vals[16]; float mx=-3.4e38f;
        #pragma unroll
        for (int t=0;t<16;t++){
            int j=t*32+lane;
            float sv = (j<nv) ? p[j] : -3.4e38f;
            vals[t]=sv; mx=fmaxf(mx,sv);
        }
        mx = wredmax(mx);
        float sum=0.f;
        #pragma unroll
        for (int t=0;t<16;t++){
            int j=t*32+lane;
            float e = (j<nv) ? expf(vals[t]-mx) : 0.f;
            vals[t]=e; sum+=e;
        }
        sum = wredsum(sum);
        float inv = 1.0f/sum;
        #pragma unroll
        for (int t=0;t<16;t++){
            int j=t*32+lane;
            float pv = vals[t]*inv;
            p[j] = pv;
            gs_[(j>>4)*17 + (j&15)] = 1.0f/(1.0f+expf(pv));  // 1 - sigmoid(pv)
        }
        const float* erow = E + ((long long)(b*LL + qi))*ML;
        #pragma unroll
        for (int t=0;t<16;t++) eb_[t*32+lane] = erow[t*32+lane];
        __syncwarp();
        float cs=0.f;
        #pragma unroll
        for (int t=0;t<16;t++) cs += gs_[lane*17+t];
        float sfx=cs;
        #pragma unroll
        for (int off=1;off<32;off<<=1){
            float o=__shfl_down_sync(0xffffffffu,sfx,off);
            if (lane+off<32) sfx+=o;
        }
        float tail = sfx - cs;
        float run=0.f, a2=0.f;
        #pragma unroll
        for (int t=15;t>=0;t--){
            run += gs_[lane*17+t];
            float P = fminf(run+tail, (float)(ML-1));
            float Pf = floorf(P);
            float fr = P - Pf;
            int pi = (int)Pf;
            int pc = (int)ceilf(P);
            a2 += fr*eb_[pc] + (1.0f-fr)*eb_[pi];
        }
        a2 = wredsum(a2);
        if (lane==0) cape[b*LL+qi] = a2 * (1.0f/ML);
        __syncwarp();
    }
    __syncthreads();

    // ---- phase 4: mha = probs @ V ----
    const int wm2=(warp&1)*32, wn2=(warp>>1)*32;
    const int kmax=(qt+1)*64;
    float acc[2][4][4];
    #pragma unroll
    for (int mi=0;mi<2;mi++)
        #pragma unroll
        for (int ni=0;ni<4;ni++)
            #pragma unroll
            for (int r=0;r<4;r++) acc[mi][ni][r]=0.f;
    for (int kc=0; kc<kmax; kc+=16){
        __syncthreads();
        #pragma unroll
        for (int r2=0;r2<2;r2++){
            int idx=r2*256+tid, kk=idx>>5, c4=(idx&31)*4;
            float4 a = *(const float4*)(v + ((long long)(b*LL+kc+kk))*DD + c4);
            VS[kk*136+c4+0]=fu(a.x); VS[kk*136+c4+1]=fu(a.y);
            VS[kk*136+c4+2]=fu(a.z); VS[kk*136+c4+3]=fu(a.w);
        }
        __syncthreads();
        #pragma unroll
        for (int s8=0;s8<2;s8++){
            int kb=s8*8;
            unsigned af[2][4];
            #pragma unroll
            for (int mi=0;mi<2;mi++){
                int r0=wm2+mi*16+ar;
                af[mi][0]=fu(S[(r0  )*SWS + kc+kb+ac  ]);
                af[mi][1]=fu(S[(r0+8)*SWS + kc+kb+ac  ]);
                af[mi][2]=fu(S[(r0  )*SWS + kc+kb+ac+4]);
                af[mi][3]=fu(S[(r0+8)*SWS + kc+kb+ac+4]);
            }
            #pragma unroll
            for (int ni=0;ni<4;ni++){
                unsigned bf[2];
                bf[0]=VS[(kb+ac  )*136 + wn2+ni*8+ar];
                bf[1]=VS[(kb+ac+4)*136 + wn2+ni*8+ar];
                mma_tf32(acc[0][ni], af[0], bf);
                mma_tf32(acc[1][ni], af[1], bf);
            }
        }
    }
    #pragma unroll
    for (int mi=0;mi<2;mi++){
        #pragma unroll
        for (int half=0; half<2; half++){
            long long gm = (long long)(b*LL + q0 + wm2 + mi*16 + ar + half*8);
            float* crow = mha + gm*DD;
            #pragma unroll
            for (int ni=0;ni<4;ni++){
                int gn = wn2 + ni*8 + ac*2;
                float2 o; o.x=acc[mi][ni][half*2+0]; o.y=acc[mi][ni][half*2+1];
                *(float2*)(crow + gn) = o;
            }
        }
    }
}

// ---------------- host orchestration ----------------
extern "C" void kernel_launch(void* const* d_in, const int* in_sizes, int n_in,
                              void* d_out, int out_size){
    (void)in_sizes; (void)n_in; (void)out_size;
    const float* item   = (const float*)d_in[0];
    const float* posemb = (const float*)d_in[1];
    const float* pre_w  = (const float*)d_in[2];
    const float* pre_b  = (const float*)d_in[3];
    const float* ln1_s  = (const float*)d_in[4];
    const float* ln1_b  = (const float*)d_in[5];
    const float* in_w   = (const float*)d_in[6];
    const float* in_b   = (const float*)d_in[7];
    const float* out_w  = (const float*)d_in[8];
    const float* out_b  = (const float*)d_in[9];
    const float* ln2_s  = (const float*)d_in[10];
    const float* ln2_b  = (const float*)d_in[11];
    const float* c1_w   = (const float*)d_in[12];
    const float* c1_b   = (const float*)d_in[13];
    const float* c2_w   = (const float*)d_in[14];
    const float* c2_b   = (const float*)d_in[15];
    const float* lnf_s  = (const float*)d_in[16];
    const float* lnf_b  = (const float*)d_in[17];
    const int* logs = (const int*)d_in[19];
    const int* poss = (const int*)d_in[20];
    const int* negs = (const int*)d_in[21];
    float* out = (float*)d_out;

    float *seqs,*Q,*q,*k,*v,*qp,*mha,*tmp,*E,*cape;
    cudaGetSymbolAddress((void**)&seqs, g_seqs);
    cudaGetSymbolAddress((void**)&Q,    g_Q);
    cudaGetSymbolAddress((void**)&q,    g_q);
    cudaGetSymbolAddress((void**)&k,    g_k);
    cudaGetSymbolAddress((void**)&v,    g_v);
    cudaGetSymbolAddress((void**)&qp,   g_qp);
    cudaGetSymbolAddress((void**)&mha,  g_mha);
    cudaGetSymbolAddress((void**)&tmp,  g_tmp);
    cudaGetSymbolAddress((void**)&E,    g_E);
    cudaGetSymbolAddress((void**)&cape, g_cape);

    const int ROWB = BL/8;
    const float scale = 0.08838834764831845f; // 1/sqrt(128)
    const int FUSED_SMEM = 64*SWS*4 + 2*128*72*4;   // 205,824 B
    static int smem_set = 0;
    if (!smem_set){
        cudaFuncSetAttribute(attn_fused, cudaFuncAttributeMaxDynamicSharedMemorySize, FUSED_SMEM);
        smem_set = 1;
    }

    embed_k<<<ROWB,256>>>(item, logs, seqs);

    for (int i=0;i<2;i++){
        const float* wq = in_w + (long long)i*3*DD*DD;
        const float* wk = wq + DD*DD;
        const float* wv = wk + DD*DD;
        const float* bq = in_b + (long long)i*3*DD;
        const float* bk = bq + DD;
        const float* bv = bk + DD;

        ln_k<false><<<ROWB,256>>>(seqs, nullptr, ln1_s+i*DD, ln1_b+i*DD, Q);

        dim3 gl(1, BL/128);
        gemm_p<true,0><<<gl,256>>>(Q,    wq,    bq,    nullptr, q,  BL, DD, DD, 1.f);
        gemm_p<true,0><<<gl,256>>>(seqs, wk,    bk,    nullptr, k,  BL, DD, DD, 1.f);
        gemm_p<true,0><<<gl,256>>>(seqs, wv,    bv,    nullptr, v,  BL, DD, DD, 1.f);
        gemm_p<true,2><<<gl,256>>>(Q,    pre_w, pre_b, nullptr, qp, BL, DD, DD, 1.f);

        // E = qp @ pos_emb   [BL, 512]
        dim3 ge(4, BL/128);
        gemm_p<false,0><<<ge,256>>>(qp, posemb, nullptr, nullptr, E, BL, ML, DD, 1.f);

        // fused attention: scores+softmax+CAPE+attn@V, attn never hits HBM
        attn_fused<<<dim3(8,BB),256,FUSED_SMEM>>>(q, k, v, E, cape, mha, scale);

        // seqs = Q + mha.out_w^T + out_b
        gemm_p<true,0><<<gl,256>>>(mha, out_w+(long long)i*DD*DD, out_b+i*DD,
                                   Q, seqs, BL, DD, DD, 1.f);

        // seqs = LN2(seqs + cape)  -> X (stored in Q buffer)
        ln_k<true><<<ROWB,256>>>(seqs, cape, ln2_s+i*DD, ln2_b+i*DD, Q);

        // FFN
        gemm_p<true,1><<<gl,256>>>(Q,   c1_w+(long long)i*DD*DD, c1_b+i*DD,
                                   nullptr, tmp, BL, DD, DD, 1.f);
        gemm_p<true,0><<<gl,256>>>(tmp, c2_w+(long long)i*DD*DD, c2_b+i*DD,
                                   Q, seqs, BL, DD, DD, 1.f);
    }

    final_k<<<ROWB,256>>>(seqs, item, lnf_s, lnf_b, poss, negs, out);
}

// round 6
// speedup vs baseline: 1.3609x; 1.3609x over previous
#include <cuda_runtime.h>
#include <math.h>

#define BB 128
#define LL 512
#define DD 128
#define BL (BB*LL)
#define ML 512

// ---------------- scratch (static device globals; no allocations) ----------------
__device__ float g_seqs[BL*DD];
__device__ float g_Q   [BL*DD];
__device__ float g_q   [BL*DD];
__device__ float g_k   [BL*DD];
__device__ float g_v   [BL*DD];
__device__ float g_qp  [BL*DD];
__device__ float g_mha [BL*DD];
__device__ float g_tmp [BL*DD];
__device__ float g_attn[BB*LL*LL];
__device__ float g_E   [BL*ML];
__device__ float g_cape[BL];

// ---------------- helpers ----------------
__device__ __forceinline__ float wredsum(float v){
    #pragma unroll
    for (int o=16;o>0;o>>=1) v += __shfl_xor_sync(0xffffffffu, v, o);
    return v;
}
__device__ __forceinline__ float wredmax(float v){
    #pragma unroll
    for (int o=16;o>0;o>>=1) v = fmaxf(v, __shfl_xor_sync(0xffffffffu, v, o));
    return v;
}
__device__ __forceinline__ void mma_tf32(float* d, const unsigned* a, const unsigned* b){
    asm volatile(
        "mma.sync.aligned.m16n8k8.row.col.f32.tf32.tf32.f32 "
        "{%0,%1,%2,%3},{%4,%5,%6,%7},{%8,%9},{%0,%1,%2,%3};"
        : "+f"(d[0]),"+f"(d[1]),"+f"(d[2]),"+f"(d[3])
        : "r"(a[0]),"r"(a[1]),"r"(a[2]),"r"(a[3]), "r"(b[0]),"r"(b[1]));
}
__device__ __forceinline__ void cpa16(void* s, const void* g){
    unsigned sa = (unsigned)__cvta_generic_to_shared(s);
    asm volatile("cp.async.cg.shared.global [%0],[%1],16;\n" :: "r"(sa),"l"(g));
}
__device__ __forceinline__ void cp_commit(){ asm volatile("cp.async.commit_group;\n"); }
template<int N> __device__ __forceinline__ void cp_wait(){ asm volatile("cp.async.wait_group %0;\n"::"n"(N)); }
__device__ __forceinline__ unsigned fu(float f){ return __float_as_uint(f); }

// ---------------- embedding gather ----------------
__global__ void embed_k(const float* __restrict__ item, const int* __restrict__ idx,
                        float* __restrict__ out){
    int row  = blockIdx.x*8 + (threadIdx.x>>5);
    int lane = threadIdx.x & 31;
    int id = idx[row];
    float4 v = *(const float4*)(item + (long long)id*DD + lane*4);
    const float s = 11.313708498984760f; // sqrt(128)
    v.x*=s; v.y*=s; v.z*=s; v.w*=s;
    *(float4*)(out + (long long)row*DD + lane*4) = v;
}

// ---------------- layernorm (optionally add per-row cape scalar first) ----------------
template<bool ADDC>
__global__ void ln_k(const float* __restrict__ x, const float* __restrict__ cape,
                     const float* __restrict__ gs, const float* __restrict__ gb,
                     float* __restrict__ y){
    int row  = blockIdx.x*8 + (threadIdx.x>>5);
    int lane = threadIdx.x & 31;
    const float* xr = x + (long long)row*DD;
    float4 v = *(const float4*)(xr + lane*4);
    if (ADDC){ float c = cape[row]; v.x+=c; v.y+=c; v.z+=c; v.w+=c; }
    float m = wredsum(v.x+v.y+v.z+v.w) * (1.0f/DD);
    float dx=v.x-m, dy=v.y-m, dz=v.z-m, dw=v.w-m;
    float var = wredsum(dx*dx+dy*dy+dz*dz+dw*dw) * (1.0f/DD);
    float r = rsqrtf(var + 1e-8f);
    float4 o;
    o.x = dx*r*gs[lane*4+0] + gb[lane*4+0];
    o.y = dy*r*gs[lane*4+1] + gb[lane*4+1];
    o.z = dz*r*gs[lane*4+2] + gb[lane*4+2];
    o.w = dw*r*gs[lane*4+3] + gb[lane*4+3];
    *(float4*)(y + (long long)row*DD + lane*4) = o;
}

// ---------------- fused causal softmax + CAPE (standalone, attn in HBM) ----------------
__global__ void softcape_k(float* __restrict__ attn, const float* __restrict__ E,
                           float* __restrict__ cape){
    __shared__ float es[8][ML];
    __shared__ float gsm[8][32][17];
    int w    = threadIdx.x>>5;
    int lane = threadIdx.x & 31;
    int row  = blockIdx.x*8 + w;
    int qi = row & (LL-1);
    float* p = attn + (long long)row*LL;
    const float* er = E + (long long)row*ML;
    #pragma unroll
    for (int t=0;t<16;t++) es[w][t*32+lane] = er[t*32+lane];

    int nv = qi+1;
    float vals[16];
    float mx = -3.4e38f;
    #pragma unroll
    for (int t=0;t<16;t++){
        int j = t*32+lane;
        float s = (j<nv) ? p[j] : -3.4e38f;
        vals[t]=s; mx = fmaxf(mx, s);
    }
    mx = wredmax(mx);
    float sum = 0.f;
    #pragma unroll
    for (int t=0;t<16;t++){
        int j = t*32+lane;
        float e = (j<nv) ? expf(vals[t]-mx) : 0.f;
        vals[t]=e; sum += e;
    }
    sum = wredsum(sum);
    float inv = 1.0f/sum;
    #pragma unroll
    for (int t=0;t<16;t++){
        int j = t*32+lane;
        float pv = vals[t]*inv;
        p[j] = pv;
        float g = 1.0f/(1.0f+expf(pv));   // 1 - sigmoid(pv); masked pv=0 -> 0.5 (matches ref)
        gsm[w][j>>4][j&15] = g;
    }
    __syncwarp();
    float cs = 0.f;
    #pragma unroll
    for (int t=0;t<16;t++) cs += gsm[w][lane][t];
    float sfx = cs;
    #pragma unroll
    for (int off=1;off<32;off<<=1){
        float o = __shfl_down_sync(0xffffffffu, sfx, off);
        if (lane+off < 32) sfx += o;
    }
    float tail = sfx - cs;
    float run = 0.f, acc = 0.f;
    #pragma unroll
    for (int t=15;t>=0;t--){
        run += gsm[w][lane][t];
        float P = run + tail;
        P = fminf(P, (float)(ML-1));
        float Pf = floorf(P);
        float fr = P - Pf;
        int pi = (int)Pf;
        int pc = (int)ceilf(P);
        float ef = es[w][pi];
        float ec = es[w][pc];
        acc += fr*ec + (1.0f-fr)*ef;
    }
    acc = wredsum(acc);
    if (lane==0) cape[row] = acc * (1.0f/LL);
}

// ---------------- final: LN + dot with pos/neg item embeddings ----------------
__global__ void final_k(const float* __restrict__ seqs, const float* __restrict__ item,
                        const float* __restrict__ gs, const float* __restrict__ gb,
                        const int* __restrict__ pos, const int* __restrict__ neg,
                        float* __restrict__ out){
    int row  = blockIdx.x*8 + (threadIdx.x>>5);
    int lane = threadIdx.x & 31;
    const float* xr = seqs + (long long)row*DD;
    float4 v = *(const float4*)(xr + lane*4);
    float m = wredsum(v.x+v.y+v.z+v.w) * (1.0f/DD);
    float dx=v.x-m, dy=v.y-m, dz=v.z-m, dw=v.w-m;
    float var = wredsum(dx*dx+dy*dy+dz*dz+dw*dw) * (1.0f/DD);
    float r = rsqrtf(var + 1e-8f);
    float f0 = dx*r*gs[lane*4+0] + gb[lane*4+0];
    float f1 = dy*r*gs[lane*4+1] + gb[lane*4+1];
    float f2 = dz*r*gs[lane*4+2] + gb[lane*4+2];
    float f3 = dw*r*gs[lane*4+3] + gb[lane*4+3];
    int pi = pos[row], ni = neg[row];
    float4 pe = *(const float4*)(item + (long long)pi*DD + lane*4);
    float4 ne = *(const float4*)(item + (long long)ni*DD + lane*4);
    float dp = f0*pe.x + f1*pe.y + f2*pe.z + f3*pe.w;
    float dn = f0*ne.x + f1*ne.y + f2*ne.z + f3*ne.w;
    dp = wredsum(dp); dn = wredsum(dn);
    if (lane==0){ out[row] = dp; out[BL+row] = dn; }
}

// ---------------- pipelined TF32 GEMM ----------------
// C = act(alpha*A.op(B)+bias)+res.  A [M,K] row-major (z-strided by sA).
// TRANSB: B [N,K] (C=A.B^T); else B [K,N].  cp.async 2-stage, 128x128x16 tiles,
// 256 thr, warp tile 64x32.
// DUAL: grid.x==2 selects (Bm,bias,C,ACT) for x=0 / (Bm2,bias2,C2,ACT2) for x=1; n0=0.
// SKIPUP: skip tiles fully above causal diagonal (scores).
// KLIM: limit K loop to m0+128 (AV with causal-zeroed probs).
template<bool TRANSB, int ACT, int ACT2, bool DUAL, bool SKIPUP, bool KLIM>
__global__ __launch_bounds__(256,2)
void gemm_p(const float* __restrict__ A, const float* __restrict__ Bm,
            const float* __restrict__ bias, const float* __restrict__ res,
            float* __restrict__ C,
            const float* __restrict__ Bm2, const float* __restrict__ bias2,
            float* __restrict__ C2,
            int M, int N, int K,
            long long sA, long long sB, long long sC, float alpha)
{
    if (SKIPUP && (int)blockIdx.x > (int)blockIdx.y) return;
    const int bz = blockIdx.z;
    A += (long long)bz*sA;
    int actv = ACT;
    if (DUAL){
        if (blockIdx.x == 1){ Bm = Bm2; bias = bias2; C = C2; actv = ACT2; }
    } else {
        Bm += (long long)bz*sB;
        C  += (long long)bz*sC;
        if (res) res += (long long)bz*sC;
    }

    __shared__ __align__(16) float As[2][128*20];
    __shared__ __align__(16) float Bs[2][2560];
    const int tid=threadIdx.x, warp=tid>>5, lane=tid&31;
    const int wm=(warp&1)*64, wn=(warp>>1)*32;
    const int m0=blockIdx.y*128;
    const int n0=DUAL ? 0 : blockIdx.x*128;
    const int ar=lane>>2, ac=lane&3;
    const int kmax = KLIM ? ((m0+128 < K) ? (m0+128) : K) : K;
    const int nk = kmax>>4;

    float acc[4][4][4];
    #pragma unroll
    for (int i=0;i<4;i++)
        #pragma unroll
        for (int j=0;j<4;j++)
            #pragma unroll
            for (int r=0;r<4;r++) acc[i][j][r]=0.f;

    // stage 0 loads
    {
        #pragma unroll
        for (int p=0;p<2;p++){
            int t=p*256+tid, row=t>>2, c4=(t&3)*4;
            cpa16(&As[0][row*20+c4], A + (long long)(m0+row)*K + c4);
        }
        if (TRANSB){
            #pragma unroll
            for (int p=0;p<2;p++){
                int t=p*256+tid, row=t>>2, c4=(t&3)*4;
                cpa16(&Bs[0][row*20+c4], Bm + (long long)(n0+row)*K + c4);
            }
        } else {
            #pragma unroll
            for (int p=0;p<2;p++){
                int t=p*256+tid, kk=t>>5, c4=(t&31)*4;
                cpa16(&Bs[0][kk*136+c4], Bm + (long long)kk*N + n0 + c4);
            }
        }
        cp_commit();
    }

    for (int i=0;i<nk;i++){
        if (i+1<nk){
            int bn=(i+1)&1, k0=(i+1)<<4;
            #pragma unroll
            for (int p=0;p<2;p++){
                int t=p*256+tid, row=t>>2, c4=(t&3)*4;
                cpa16(&As[bn][row*20+c4], A + (long long)(m0+row)*K + k0 + c4);
            }
            if (TRANSB){
                #pragma unroll
                for (int p=0;p<2;p++){
                    int t=p*256+tid, row=t>>2, c4=(t&3)*4;
                    cpa16(&Bs[bn][row*20+c4], Bm + (long long)(n0+row)*K + k0 + c4);
                }
            } else {
                #pragma unroll
                for (int p=0;p<2;p++){
                    int t=p*256+tid, kk=t>>5, c4=(t&31)*4;
                    cpa16(&Bs[bn][kk*136+c4], Bm + (long long)(k0+kk)*N + n0 + c4);
                }
            }
            cp_commit();
            cp_wait<1>();
        } else {
            cp_wait<0>();
        }
        __syncthreads();
        const int bc=i&1;
        #pragma unroll
        for (int s8=0;s8<2;s8++){
            const int kb=s8*8;
            unsigned af[4][4];
            #pragma unroll
            for (int mi=0;mi<4;mi++){
                int r0=wm+mi*16+ar;
                af[mi][0]=fu(As[bc][(r0  )*20+kb+ac  ]);
                af[mi][1]=fu(As[bc][(r0+8)*20+kb+ac  ]);
                af[mi][2]=fu(As[bc][(r0  )*20+kb+ac+4]);
                af[mi][3]=fu(As[bc][(r0+8)*20+kb+ac+4]);
            }
            #pragma unroll
            for (int ni=0;ni<4;ni++){
                unsigned bf[2];
                if (TRANSB){
                    int nr=wn+ni*8+ar;
                    bf[0]=fu(Bs[bc][nr*20+kb+ac  ]);
                    bf[1]=fu(Bs[bc][nr*20+kb+ac+4]);
                } else {
                    int nc=wn+ni*8+ar;
                    bf[0]=fu(Bs[bc][(kb+ac  )*136+nc]);
                    bf[1]=fu(Bs[bc][(kb+ac+4)*136+nc]);
                }
                #pragma unroll
                for (int mi=0;mi<4;mi++) mma_tf32(acc[mi][ni], af[mi], bf);
            }
        }
        __syncthreads();
    }

    const int er=lane>>2, ec=(lane&3)*2;
    #pragma unroll
    for (int mi=0;mi<4;mi++){
        #pragma unroll
        for (int half=0; half<2; half++){
            long long gm = m0 + wm + mi*16 + er + half*8;
            float* crow = C + gm*(long long)N;
            const float* rrow = res ? (res + gm*(long long)N) : nullptr;
            #pragma unroll
            for (int ni=0;ni<4;ni++){
                int gn = n0 + wn + ni*8 + ec;
                float v0 = acc[mi][ni][half*2+0]*alpha;
                float v1 = acc[mi][ni][half*2+1]*alpha;
                if (bias){ v0 += bias[gn]; v1 += bias[gn+1]; }
                if (actv==1){ v0 = fmaxf(v0,0.f); v1 = fmaxf(v1,0.f); }
                if (actv==2){ v0 = v0/(1.0f+expf(-v0)); v1 = v1/(1.0f+expf(-v1)); }
                if (rrow){ v0 += rrow[gn]; v1 += rrow[gn+1]; }
                float2 o; o.x=v0; o.y=v1;
                *(float2*)(crow + gn) = o;
            }
        }
    }
}

// ---------------- host orchestration ----------------
extern "C" void kernel_launch(void* const* d_in, const int* in_sizes, int n_in,
                              void* d_out, int out_size){
    (void)in_sizes; (void)n_in; (void)out_size;
    const float* item   = (const float*)d_in[0];
    const float* posemb = (const float*)d_in[1];
    const float* pre_w  = (const float*)d_in[2];
    const float* pre_b  = (const float*)d_in[3];
    const float* ln1_s  = (const float*)d_in[4];
    const float* ln1_b  = (const float*)d_in[5];
    const float* in_w   = (const float*)d_in[6];
    const float* in_b   = (const float*)d_in[7];
    const float* out_w  = (const float*)d_in[8];
    const float* out_b  = (const float*)d_in[9];
    const float* ln2_s  = (const float*)d_in[10];
    const float* ln2_b  = (const float*)d_in[11];
    const float* c1_w   = (const float*)d_in[12];
    const float* c1_b   = (const float*)d_in[13];
    const float* c2_w   = (const float*)d_in[14];
    const float* c2_b   = (const float*)d_in[15];
    const float* lnf_s  = (const float*)d_in[16];
    const float* lnf_b  = (const float*)d_in[17];
    const int* logs = (const int*)d_in[19];
    const int* poss = (const int*)d_in[20];
    const int* negs = (const int*)d_in[21];
    float* out = (float*)d_out;

    float *seqs,*Q,*q,*k,*v,*qp,*mha,*tmp,*attn,*E,*cape;
    cudaGetSymbolAddress((void**)&seqs, g_seqs);
    cudaGetSymbolAddress((void**)&Q,    g_Q);
    cudaGetSymbolAddress((void**)&q,    g_q);
    cudaGetSymbolAddress((void**)&k,    g_k);
    cudaGetSymbolAddress((void**)&v,    g_v);
    cudaGetSymbolAddress((void**)&qp,   g_qp);
    cudaGetSymbolAddress((void**)&mha,  g_mha);
    cudaGetSymbolAddress((void**)&tmp,  g_tmp);
    cudaGetSymbolAddress((void**)&attn, g_attn);
    cudaGetSymbolAddress((void**)&E,    g_E);
    cudaGetSymbolAddress((void**)&cape, g_cape);

    const int ROWB = BL/8;
    const float scale = 0.08838834764831845f; // 1/sqrt(128)

    embed_k<<<ROWB,256>>>(item, logs, seqs);

    for (int i=0;i<2;i++){
        const float* wq = in_w + (long long)i*3*DD*DD;
        const float* wk = wq + DD*DD;
        const float* wv = wk + DD*DD;
        const float* bq = in_b + (long long)i*3*DD;
        const float* bk = bq + DD;
        const float* bv = bk + DD;

        ln_k<false><<<ROWB,256>>>(seqs, nullptr, ln1_s+i*DD, ln1_b+i*DD, Q);

        // dual GEMMs: (q, qp) from Q;  (k, v) from seqs
        dim3 gd(2, BL/128);
        gemm_p<true,0,2,true,false,false><<<gd,256>>>(Q, wq, bq, nullptr, q,
                                                      pre_w, pre_b, qp,
                                                      BL, DD, DD, 0,0,0, 1.f);
        gemm_p<true,0,0,true,false,false><<<gd,256>>>(seqs, wk, bk, nullptr, k,
                                                      wv, bv, v,
                                                      BL, DD, DD, 0,0,0, 1.f);

        // E = qp @ pos_emb   [BL, 512]
        dim3 ge(4, BL/128);
        gemm_p<false,0,0,false,false,false><<<ge,256>>>(qp, posemb, nullptr, nullptr, E,
                                                        nullptr,nullptr,nullptr,
                                                        BL, ML, DD, 0,0,0, 1.f);

        // scores = q.k^T * scale  (skip fully-masked upper tiles)
        dim3 gsc(4,4,BB);
        gemm_p<true,0,0,false,true,false><<<gsc,256>>>(q, k, nullptr, nullptr, attn,
            nullptr,nullptr,nullptr,
            LL, LL, DD, (long long)LL*DD, (long long)LL*DD, (long long)LL*LL, scale);

        // fused softmax + CAPE (writes normalized attn incl. exact-0 masked, + cape)
        softcape_k<<<ROWB,256>>>(attn, E, cape);

        // mha = attn.v  (K-loop limited by causal zeros)
        dim3 gav(1,4,BB);
        gemm_p<false,0,0,false,false,true><<<gav,256>>>(attn, v, nullptr, nullptr, mha,
            nullptr,nullptr,nullptr,
            LL, DD, LL, (long long)LL*LL, (long long)LL*DD, (long long)LL*DD, 1.f);

        // seqs = Q + mha.out_w^T + out_b
        dim3 gl(1, BL/128);
        gemm_p<true,0,0,false,false,false><<<gl,256>>>(mha, out_w+(long long)i*DD*DD,
                                                       out_b+i*DD, Q, seqs,
                                                       nullptr,nullptr,nullptr,
                                                       BL, DD, DD, 0,0,0, 1.f);

        // seqs = LN2(seqs + cape)  -> X (stored in Q buffer)
        ln_k<true><<<ROWB,256>>>(seqs, cape, ln2_s+i*DD, ln2_b+i*DD, Q);

        // FFN
        gemm_p<true,1,0,false,false,false><<<gl,256>>>(Q, c1_w+(long long)i*DD*DD,
                                                       c1_b+i*DD, nullptr, tmp,
                                                       nullptr,nullptr,nullptr,
                                                       BL, DD, DD, 0,0,0, 1.f);
        gemm_p<true,0,0,false,false,false><<<gl,256>>>(tmp, c2_w+(long long)i*DD*DD,
                                                       c2_b+i*DD, Q, seqs,
                                                       nullptr,nullptr,nullptr,
                                                       BL, DD, DD, 0,0,0, 1.f);
    }

    final_k<<<ROWB,256>>>(seqs, item, lnf_s, lnf_b, poss, negs, out);
}

// round 8
// speedup vs baseline: 1.3643x; 1.0025x over previous
#include <cuda_runtime.h>
#include <math.h>

#define BB 128
#define LL 512
#define DD 128
#define BL (BB*LL)
#define ML 512

// ---------------- scratch (static device globals; no allocations) ----------------
__device__ float g_seqs[BL*DD];
__device__ float g_Q   [BL*DD];
__device__ float g_q   [BL*DD];
__device__ float g_k   [BL*DD];
__device__ float g_v   [BL*DD];
__device__ float g_qp  [BL*DD];
__device__ float g_mha [BL*DD];
__device__ float g_tmp [BL*DD];
__device__ float g_attn[BB*LL*LL];
__device__ float g_E   [BL*ML];
__device__ float g_cape[BL];

// ---------------- helpers ----------------
__device__ __forceinline__ float wredsum(float v){
    #pragma unroll
    for (int o=16;o>0;o>>=1) v += __shfl_xor_sync(0xffffffffu, v, o);
    return v;
}
__device__ __forceinline__ float wredmax(float v){
    #pragma unroll
    for (int o=16;o>0;o>>=1) v = fmaxf(v, __shfl_xor_sync(0xffffffffu, v, o));
    return v;
}
__device__ __forceinline__ void mma_tf32(float* d, const unsigned* a, const unsigned* b){
    asm volatile(
        "mma.sync.aligned.m16n8k8.row.col.f32.tf32.tf32.f32 "
        "{%0,%1,%2,%3},{%4,%5,%6,%7},{%8,%9},{%0,%1,%2,%3};"
        : "+f"(d[0]),"+f"(d[1]),"+f"(d[2]),"+f"(d[3])
        : "r"(a[0]),"r"(a[1]),"r"(a[2]),"r"(a[3]), "r"(b[0]),"r"(b[1]));
}
__device__ __forceinline__ void cpa16(void* s, const void* g){
    unsigned sa = (unsigned)__cvta_generic_to_shared(s);
    asm volatile("cp.async.cg.shared.global [%0],[%1],16;\n" :: "r"(sa),"l"(g));
}
__device__ __forceinline__ void cp_commit(){ asm volatile("cp.async.commit_group;\n"); }
template<int N> __device__ __forceinline__ void cp_wait(){ asm volatile("cp.async.wait_group %0;\n"::"n"(N)); }
__device__ __forceinline__ unsigned fu(float f){ return __float_as_uint(f); }

// ---------------- embedding gather ----------------
__global__ void embed_k(const float* __restrict__ item, const int* __restrict__ idx,
                        float* __restrict__ out){
    int row  = blockIdx.x*8 + (threadIdx.x>>5);
    int lane = threadIdx.x & 31;
    int id = idx[row];
    float4 v = *(const float4*)(item + (long long)id*DD + lane*4);
    const float s = 11.313708498984760f; // sqrt(128)
    v.x*=s; v.y*=s; v.z*=s; v.w*=s;
    *(float4*)(out + (long long)row*DD + lane*4) = v;
}

// ---------------- layernorm (optionally add per-row cape scalar first) ----------------
template<bool ADDC>
__global__ void ln_k(const float* __restrict__ x, const float* __restrict__ cape,
                     const float* __restrict__ gs, const float* __restrict__ gb,
                     float* __restrict__ y){
    int row  = blockIdx.x*8 + (threadIdx.x>>5);
    int lane = threadIdx.x & 31;
    const float* xr = x + (long long)row*DD;
    float4 v = *(const float4*)(xr + lane*4);
    if (ADDC){ float c = cape[row]; v.x+=c; v.y+=c; v.z+=c; v.w+=c; }
    float m = wredsum(v.x+v.y+v.z+v.w) * (1.0f/DD);
    float dx=v.x-m, dy=v.y-m, dz=v.z-m, dw=v.w-m;
    float var = wredsum(dx*dx+dy*dy+dz*dz+dw*dw) * (1.0f/DD);
    float r = rsqrtf(var + 1e-8f);
    float4 o;
    o.x = dx*r*gs[lane*4+0] + gb[lane*4+0];
    o.y = dy*r*gs[lane*4+1] + gb[lane*4+1];
    o.z = dz*r*gs[lane*4+2] + gb[lane*4+2];
    o.w = dw*r*gs[lane*4+3] + gb[lane*4+3];
    *(float4*)(y + (long long)row*DD + lane*4) = o;
}

// ---------------- fused causal softmax + CAPE (standalone, attn in HBM) ----------------
__global__ void softcape_k(float* __restrict__ attn, const float* __restrict__ E,
                           float* __restrict__ cape){
    __shared__ float es[8][ML];
    __shared__ float gsm[8][32][17];
    int w    = threadIdx.x>>5;
    int lane = threadIdx.x & 31;
    int row  = blockIdx.x*8 + w;
    int qi = row & (LL-1);
    float* p = attn + (long long)row*LL;
    const float* er = E + (long long)row*ML;
    #pragma unroll
    for (int t=0;t<16;t++) es[w][t*32+lane] = er[t*32+lane];

    int nv = qi+1;
    float vals[16];
    float mx = -3.4e38f;
    #pragma unroll
    for (int t=0;t<16;t++){
        int j = t*32+lane;
        float s = (j<nv) ? p[j] : -3.4e38f;
        vals[t]=s; mx = fmaxf(mx, s);
    }
    mx = wredmax(mx);
    float sum = 0.f;
    #pragma unroll
    for (int t=0;t<16;t++){
        int j = t*32+lane;
        float e = (j<nv) ? expf(vals[t]-mx) : 0.f;
        vals[t]=e; sum += e;
    }
    sum = wredsum(sum);
    float inv = 1.0f/sum;
    #pragma unroll
    for (int t=0;t<16;t++){
        int j = t*32+lane;
        float pv = vals[t]*inv;
        p[j] = pv;
        float g = 1.0f/(1.0f+expf(pv));   // 1 - sigmoid(pv); masked pv=0 -> 0.5 (matches ref)
        gsm[w][j>>4][j&15] = g;
    }
    __syncwarp();
    float cs = 0.f;
    #pragma unroll
    for (int t=0;t<16;t++) cs += gsm[w][lane][t];
    float sfx = cs;
    #pragma unroll
    for (int off=1;off<32;off<<=1){
        float o = __shfl_down_sync(0xffffffffu, sfx, off);
        if (lane+off < 32) sfx += o;
    }
    float tail = sfx - cs;
    float run = 0.f, acc = 0.f;
    #pragma unroll
    for (int t=15;t>=0;t--){
        run += gsm[w][lane][t];
        float P = run + tail;
        P = fminf(P, (float)(ML-1));
        float Pf = floorf(P);
        float fr = P - Pf;
        int pi = (int)Pf;
        int pc = (int)ceilf(P);
        float ef = es[w][pi];
        float ec = es[w][pc];
        acc += fr*ec + (1.0f-fr)*ef;
    }
    acc = wredsum(acc);
    if (lane==0) cape[row] = acc * (1.0f/LL);
}

// ---------------- final: LN + dot with pos/neg item embeddings ----------------
__global__ void final_k(const float* __restrict__ seqs, const float* __restrict__ item,
                        const float* __restrict__ gs, const float* __restrict__ gb,
                        const int* __restrict__ pos, const int* __restrict__ neg,
                        float* __restrict__ out){
    int row  = blockIdx.x*8 + (threadIdx.x>>5);
    int lane = threadIdx.x & 31;
    const float* xr = seqs + (long long)row*DD;
    float4 v = *(const float4*)(xr + lane*4);
    float m = wredsum(v.x+v.y+v.z+v.w) * (1.0f/DD);
    float dx=v.x-m, dy=v.y-m, dz=v.z-m, dw=v.w-m;
    float var = wredsum(dx*dx+dy*dy+dz*dz+dw*dw) * (1.0f/DD);
    float r = rsqrtf(var + 1e-8f);
    float f0 = dx*r*gs[lane*4+0] + gb[lane*4+0];
    float f1 = dy*r*gs[lane*4+1] + gb[lane*4+1];
    float f2 = dz*r*gs[lane*4+2] + gb[lane*4+2];
    float f3 = dw*r*gs[lane*4+3] + gb[lane*4+3];
    int pi = pos[row], ni = neg[row];
    float4 pe = *(const float4*)(item + (long long)pi*DD + lane*4);
    float4 ne = *(const float4*)(item + (long long)ni*DD + lane*4);
    float dp = f0*pe.x + f1*pe.y + f2*pe.z + f3*pe.w;
    float dn = f0*ne.x + f1*ne.y + f2*ne.z + f3*ne.w;
    dp = wredsum(dp); dn = wredsum(dn);
    if (lane==0){ out[row] = dp; out[BL+row] = dn; }
}

// ---------------- pipelined TF32 GEMM ----------------
// C = act(alpha*A.op(B)+bias)+res.  A [M,K] row-major (z-strided by sA).
// TRANSB: B [N,K] (C=A.B^T); else B [K,N].  cp.async 2-stage, 128x128x16 tiles,
// 256 thr, warp tile 64x32.
// DUAL: grid.x==2 selects (Bm,bias,C,ACT) for x=0 / (Bm2,bias2,C2,ACT2) for x=1; n0=0.
// SKIPUP: skip tiles fully above causal diagonal (scores).
// KLIM: limit K loop to m0+128 (AV with causal-zeroed probs).
template<bool TRANSB, int ACT, int ACT2, bool DUAL, bool SKIPUP, bool KLIM>
__global__ __launch_bounds__(256,2)
void gemm_p(const float* __restrict__ A, const float* __restrict__ Bm,
            const float* __restrict__ bias, const float* __restrict__ res,
            float* __restrict__ C,
            const float* __restrict__ Bm2, const float* __restrict__ bias2,
            float* __restrict__ C2,
            int M, int N, int K,
            long long sA, long long sB, long long sC, float alpha)
{
    if (SKIPUP && (int)blockIdx.x > (int)blockIdx.y) return;
    const int bz = blockIdx.z;
    A += (long long)bz*sA;
    int actv = ACT;
    if (DUAL){
        if (blockIdx.x == 1){ Bm = Bm2; bias = bias2; C = C2; actv = ACT2; }
    } else {
        Bm += (long long)bz*sB;
        C  += (long long)bz*sC;
        if (res) res += (long long)bz*sC;
    }

    __shared__ __align__(16) float As[2][128*20];
    __shared__ __align__(16) float Bs[2][2560];
    const int tid=threadIdx.x, warp=tid>>5, lane=tid&31;
    const int wm=(warp&1)*64, wn=(warp>>1)*32;
    const int m0=blockIdx.y*128;
    const int n0=DUAL ? 0 : blockIdx.x*128;
    const int ar=lane>>2, ac=lane&3;
    const int kmax = KLIM ? ((m0+128 < K) ? (m0+128) : K) : K;
    const int nk = kmax>>4;

    float acc[4][4][4];
    #pragma unroll
    for (int i=0;i<4;i++)
        #pragma unroll
        for (int j=0;j<4;j++)
            #pragma unroll
            for (int r=0;r<4;r++) acc[i][j][r]=0.f;

    // stage 0 loads
    {
        #pragma unroll
        for (int p=0;p<2;p++){
            int t=p*256+tid, row=t>>2, c4=(t&3)*4;
            cpa16(&As[0][row*20+c4], A + (long long)(m0+row)*K + c4);
        }
        if (TRANSB){
            #pragma unroll
            for (int p=0;p<2;p++){
                int t=p*256+tid, row=t>>2, c4=(t&3)*4;
                cpa16(&Bs[0][row*20+c4], Bm + (long long)(n0+row)*K + c4);
            }
        } else {
            #pragma unroll
            for (int p=0;p<2;p++){
                int t=p*256+tid, kk=t>>5, c4=(t&31)*4;
                cpa16(&Bs[0][kk*136+c4], Bm + (long long)kk*N + n0 + c4);
            }
        }
        cp_commit();
    }

    for (int i=0;i<nk;i++){
        if (i+1<nk){
            int bn=(i+1)&1, k0=(i+1)<<4;
            #pragma unroll
            for (int p=0;p<2;p++){
                int t=p*256+tid, row=t>>2, c4=(t&3)*4;
                cpa16(&As[bn][row*20+c4], A + (long long)(m0+row)*K + k0 + c4);
            }
            if (TRANSB){
                #pragma unroll
                for (int p=0;p<2;p++){
                    int t=p*256+tid, row=t>>2, c4=(t&3)*4;
                    cpa16(&Bs[bn][row*20+c4], Bm + (long long)(n0+row)*K + k0 + c4);
                }
            } else {
                #pragma unroll
                for (int p=0;p<2;p++){
                    int t=p*256+tid, kk=t>>5, c4=(t&31)*4;
                    cpa16(&Bs[bn][kk*136+c4], Bm + (long long)(k0+kk)*N + n0 + c4);
                }
            }
            cp_commit();
            cp_wait<1>();
        } else {
            cp_wait<0>();
        }
        __syncthreads();
        const int bc=i&1;
        #pragma unroll
        for (int s8=0;s8<2;s8++){
            const int kb=s8*8;
            unsigned af[4][4];
            #pragma unroll
            for (int mi=0;mi<4;mi++){
                int r0=wm+mi*16+ar;
                af[mi][0]=fu(As[bc][(r0  )*20+kb+ac  ]);
                af[mi][1]=fu(As[bc][(r0+8)*20+kb+ac  ]);
                af[mi][2]=fu(As[bc][(r0  )*20+kb+ac+4]);
                af[mi][3]=fu(As[bc][(r0+8)*20+kb+ac+4]);
            }
            #pragma unroll
            for (int ni=0;ni<4;ni++){
                unsigned bf[2];
                if (TRANSB){
                    int nr=wn+ni*8+ar;
                    bf[0]=fu(Bs[bc][nr*20+kb+ac  ]);
                    bf[1]=fu(Bs[bc][nr*20+kb+ac+4]);
                } else {
                    int nc=wn+ni*8+ar;
                    bf[0]=fu(Bs[bc][(kb+ac  )*136+nc]);
                    bf[1]=fu(Bs[bc][(kb+ac+4)*136+nc]);
                }
                #pragma unroll
                for (int mi=0;mi<4;mi++) mma_tf32(acc[mi][ni], af[mi], bf);
            }
        }
        __syncthreads();
    }

    const int er=lane>>2, ec=(lane&3)*2;
    #pragma unroll
    for (int mi=0;mi<4;mi++){
        #pragma unroll
        for (int half=0; half<2; half++){
            long long gm = m0 + wm + mi*16 + er + half*8;
            float* crow = C + gm*(long long)N;
            const float* rrow = res ? (res + gm*(long long)N) : nullptr;
            #pragma unroll
            for (int ni=0;ni<4;ni++){
                int gn = n0 + wn + ni*8 + ec;
                float v0 = acc[mi][ni][half*2+0]*alpha;
                float v1 = acc[mi][ni][half*2+1]*alpha;
                if (bias){ v0 += bias[gn]; v1 += bias[gn+1]; }
                if (actv==1){ v0 = fmaxf(v0,0.f); v1 = fmaxf(v1,0.f); }
                if (actv==2){ v0 = v0/(1.0f+expf(-v0)); v1 = v1/(1.0f+expf(-v1)); }
                if (rrow){ v0 += rrow[gn]; v1 += rrow[gn+1]; }
                float2 o; o.x=v0; o.y=v1;
                *(float2*)(crow + gn) = o;
            }
        }
    }
}

// ---------------- host orchestration ----------------
extern "C" void kernel_launch(void* const* d_in, const int* in_sizes, int n_in,
                              void* d_out, int out_size){
    (void)in_sizes; (void)n_in; (void)out_size;
    const float* item   = (const float*)d_in[0];
    const float* posemb = (const float*)d_in[1];
    const float* pre_w  = (const float*)d_in[2];
    const float* pre_b  = (const float*)d_in[3];
    const float* ln1_s  = (const float*)d_in[4];
    const float* ln1_b  = (const float*)d_in[5];
    const float* in_w   = (const float*)d_in[6];
    const float* in_b   = (const float*)d_in[7];
    const float* out_w  = (const float*)d_in[8];
    const float* out_b  = (const float*)d_in[9];
    const float* ln2_s  = (const float*)d_in[10];
    const float* ln2_b  = (const float*)d_in[11];
    const float* c1_w   = (const float*)d_in[12];
    const float* c1_b   = (const float*)d_in[13];
    const float* c2_w   = (const float*)d_in[14];
    const float* c2_b   = (const float*)d_in[15];
    const float* lnf_s  = (const float*)d_in[16];
    const float* lnf_b  = (const float*)d_in[17];
    const int* logs = (const int*)d_in[19];
    const int* poss = (const int*)d_in[20];
    const int* negs = (const int*)d_in[21];
    float* out = (float*)d_out;

    float *seqs,*Q,*q,*k,*v,*qp,*mha,*tmp,*attn,*E,*cape;
    cudaGetSymbolAddress((void**)&seqs, g_seqs);
    cudaGetSymbolAddress((void**)&Q,    g_Q);
    cudaGetSymbolAddress((void**)&q,    g_q);
    cudaGetSymbolAddress((void**)&k,    g_k);
    cudaGetSymbolAddress((void**)&v,    g_v);
    cudaGetSymbolAddress((void**)&qp,   g_qp);
    cudaGetSymbolAddress((void**)&mha,  g_mha);
    cudaGetSymbolAddress((void**)&tmp,  g_tmp);
    cudaGetSymbolAddress((void**)&attn, g_attn);
    cudaGetSymbolAddress((void**)&E,    g_E);
    cudaGetSymbolAddress((void**)&cape, g_cape);

    const int ROWB = BL/8;
    const float scale = 0.08838834764831845f; // 1/sqrt(128)

    embed_k<<<ROWB,256>>>(item, logs, seqs);

    for (int i=0;i<2;i++){
        const float* wq = in_w + (long long)i*3*DD*DD;
        const float* wk = wq + DD*DD;
        const float* wv = wk + DD*DD;
        const float* bq = in_b + (long long)i*3*DD;
        const float* bk = bq + DD;
        const float* bv = bk + DD;

        ln_k<false><<<ROWB,256>>>(seqs, nullptr, ln1_s+i*DD, ln1_b+i*DD, Q);

        // dual GEMMs: (q, qp) from Q;  (k, v) from seqs
        dim3 gd(2, BL/128);
        gemm_p<true,0,2,true,false,false><<<gd,256>>>(Q, wq, bq, nullptr, q,
                                                      pre_w, pre_b, qp,
                                                      BL, DD, DD, 0,0,0, 1.f);
        gemm_p<true,0,0,true,false,false><<<gd,256>>>(seqs, wk, bk, nullptr, k,
                                                      wv, bv, v,
                                                      BL, DD, DD, 0,0,0, 1.f);

        // E = qp @ pos_emb   [BL, 512]
        dim3 ge(4, BL/128);
        gemm_p<false,0,0,false,false,false><<<ge,256>>>(qp, posemb, nullptr, nullptr, E,
                                                        nullptr,nullptr,nullptr,
                                                        BL, ML, DD, 0,0,0, 1.f);

        // scores = q.k^T * scale  (skip fully-masked upper tiles)
        dim3 gsc(4,4,BB);
        gemm_p<true,0,0,false,true,false><<<gsc,256>>>(q, k, nullptr, nullptr, attn,
            nullptr,nullptr,nullptr,
            LL, LL, DD, (long long)LL*DD, (long long)LL*DD, (long long)LL*LL, scale);

        // fused softmax + CAPE (writes normalized attn incl. exact-0 masked, + cape)
        softcape_k<<<ROWB,256>>>(attn, E, cape);

        // mha = attn.v  (K-loop limited by causal zeros)
        dim3 gav(1,4,BB);
        gemm_p<false,0,0,false,false,true><<<gav,256>>>(attn, v, nullptr, nullptr, mha,
            nullptr,nullptr,nullptr,
            LL, DD, LL, (long long)LL*LL, (long long)LL*DD, (long long)LL*DD, 1.f);

        // seqs = Q + mha.out_w^T + out_b
        dim3 gl(1, BL/128);
        gemm_p<true,0,0,false,false,false><<<gl,256>>>(mha, out_w+(long long)i*DD*DD,
                                                       out_b+i*DD, Q, seqs,
                                                       nullptr,nullptr,nullptr,
                                                       BL, DD, DD, 0,0,0, 1.f);

        // seqs = LN2(seqs + cape)  -> X (stored in Q buffer)
        ln_k<true><<<ROWB,256>>>(seqs, cape, ln2_s+i*DD, ln2_b+i*DD, Q);

        // FFN
        gemm_p<true,1,0,false,false,false><<<gl,256>>>(Q, c1_w+(long long)i*DD*DD,
                                                       c1_b+i*DD, nullptr, tmp,
                                                       nullptr,nullptr,nullptr,
                                                       BL, DD, DD, 0,0,0, 1.f);
        gemm_p<true,0,0,false,false,false><<<gl,256>>>(tmp, c2_w+(long long)i*DD*DD,
                                                       c2_b+i*DD, Q, seqs,
                                                       nullptr,nullptr,nullptr,
                                                       BL, DD, DD, 0,0,0, 1.f);
    }

    final_k<<<ROWB,256>>>(seqs, item, lnf_s, lnf_b, poss, negs, out);
}